// round 9
// baseline (speedup 1.0000x reference)
#include <cuda_runtime.h>

// SCCT_NGT: 5000-step explicit PDE loop on NX=64 with tiny MLP closure,
// then phi2 = mean(u^2) and histogram entropy H of |u|/max.
//
// One persistent CTA, 256 threads = 8 warps (2/SMSP). Thread t: point
// p = t>>2, sub = t&3 owns an 8-unit slice of the 32 hidden units.
// Per-SMSP MUFU floor: 16 warp-TANH/step @ rt 8 = 128 cyc/step.
//
// R9 (= R7 + split store, all scalar; R8's f32x2 pack/unpack reverted):
// after ONE shfl_xor(1) hop, lane sub=0 holds sum(units 0..15) and lane
// sub=2 holds sum(units 16..31). Lane 0 stores base+DTg*sA to bufM, lane 2
// stores DTg*sB to bufP; readers reconstruct u = M + P. Saves the second
// 26-cyc shfl hop at the cost of ~8 cyc extra head latency.

#define NXc 64
#define HIDc 16
#define UPT 8   // hidden units per thread

__device__ __forceinline__ float tanhf_mufu(float x) {
    float y; asm("tanh.approx.f32 %0, %1;" : "=f"(y) : "f"(x)); return y;
}

__global__ __launch_bounds__(256, 1)
void scct_kernel(const float* __restrict__ u0,
                 const float* __restrict__ w1, const float* __restrict__ b1,
                 const float* __restrict__ w2, const float* __restrict__ b2,
                 const float* __restrict__ wc, const float* __restrict__ bc,
                 const float* __restrict__ gammap, const int* __restrict__ Ntp,
                 float* __restrict__ out)
{
    __shared__ float bufM[2][NXc + 2];   // main part (lane sub==0 writes)
    __shared__ float bufP[2][NXc + 2];   // partial (lane sub==2 writes); u = M+P
    __shared__ float s2red[NXc];
    __shared__ float vmred[NXc];
    __shared__ int   hist[NXc];

    const int t   = threadIdx.x;
    const int p   = t >> 2;      // grid point 0..63
    const int sub = t & 3;       // 4 threads per point
    const float bmask = (p == 0 || p == NXc - 1) ? 0.0f : 1.0f;  // Dirichlet

    const float gamma = gammap[0];
    const int   Nt    = Ntp[0];
    const float bcv   = bc[0];

    const float DTf  = (float)1e-4;
    const float R2DX = 31.5f;     // 1/(2*DX), exact
    const float RDX2 = 3969.0f;   // 1/DX^2, exact

    // Masked per-thread update constants (zero on boundary threads -> un = 0).
    const float DTf_m  = DTf * bmask;
    const float DTg_m  = DTf * gamma * bmask;
    const float DTgb_m = DTf * gamma * bcv * bmask;
    const float K08R   = 0.8f * RDX2;        // core: (um+up) coeff
    const float C1     = 0.5f - 2.0f * K08R; // core: uc coeff

    // This thread's 8-unit weight slice, stencil pre-folded:
    //   z_j = um*(RDX2*wq - R2DX*wb) + uc*(wa - 2*RDX2*wq)
    //       + up*(R2DX*wb + RDX2*wq) + bb
    const float* W  = (sub >> 1) ? w2 : w1;
    const float* Bp = (sub >> 1) ? b2 : b1;
    const int j0 = (sub & 1) * UPT;
    float Aw[UPT], Bw[UPT], Cw[UPT], bb[UPT], cwr[UPT];
#pragma unroll
    for (int k = 0; k < UPT; k++) {
        int j = j0 + k;
        float wa = W[j * 3 + 0];
        float wb = W[j * 3 + 1];
        float wq = W[j * 3 + 2];
        Aw[k]  = RDX2 * wq - R2DX * wb;
        Bw[k]  = wa - 2.0f * RDX2 * wq;
        Cw[k]  = R2DX * wb + RDX2 * wq;
        bb[k]  = Bp[j];
        cwr[k] = wc[(sub >> 1) * HIDc + j];
    }

    // Init shared buffers (ghosts zero everywhere; never rewritten).
    if (t < NXc + 2) {
        bufM[0][t] = 0.0f; bufM[1][t] = 0.0f;
        bufP[0][t] = 0.0f; bufP[1][t] = 0.0f;
    }
    __syncthreads();
    if (t < NXc) bufM[0][t + 1] = u0[t];
    __syncthreads();

    int cur = 0;
    for (int it = 0; it < Nt; ++it) {
        const float um = bufM[cur][p]     + bufP[cur][p];
        const float uc = bufM[cur][p + 1] + bufP[cur][p + 1];
        const float up = bufM[cur][p + 2] + bufP[cur][p + 2];

        // core = 0.8*lap + 0.5*uc - uc^3 (folded); parallel to the tanh block
        const float core = fmaf(um + up, K08R, fmaf(uc, C1, -(uc * uc * uc)));
        const float base = fmaf(DTf_m, core, uc * bmask) + DTgb_m;

        float s0 = 0.0f, s1 = 0.0f;
#pragma unroll
        for (int k = 0; k < UPT; k += 2) {
            float za = fmaf(up, Cw[k],   fmaf(uc, Bw[k],   fmaf(um, Aw[k],   bb[k])));
            float zb = fmaf(up, Cw[k+1], fmaf(uc, Bw[k+1], fmaf(um, Aw[k+1], bb[k+1])));
            float ta = tanhf_mufu(za);
            float tb = tanhf_mufu(zb);
            s0 = fmaf(cwr[k],   ta, s0);
            s1 = fmaf(cwr[k+1], tb, s1);
        }
        float s = s0 + s1;
        // One hop: lane sub=0 gets units 0..15 sum, lane sub=2 gets 16..31.
        s += __shfl_xor_sync(0xffffffffu, s, 1);

        if (sub == 0)      bufM[cur ^ 1][p + 1] = fmaf(DTg_m, s, base);
        else if (sub == 2) bufP[cur ^ 1][p + 1] = DTg_m * s;
        __syncthreads();
        cur ^= 1;
    }

    // ---- Final statistics ----
    if (t < NXc) {
        float v = bufM[cur][t + 1] + bufP[cur][t + 1];
        out[t]     = v;
        s2red[t]   = v * v;
        vmred[t]   = fabsf(v);
        hist[t]    = 0;
    }
    __syncthreads();

    if (t == 0) {
        float s2 = 0.0f, vmax = 0.0f;
        for (int i = 0; i < NXc; i++) {
            s2   += s2red[i];
            vmax  = fmaxf(vmax, vmred[i]);
        }
        out[NXc] = s2 * (1.0f / 64.0f);   // phi2 = mean(u^2)

        const float vden = fmaxf(vmax, 1e-12f);
        for (int i = 0; i < NXc; i++) {
            float vn = vmred[i] / vden;   // in [0, 1]
            int b = (int)floorf(vn * 64.0f);
            if (b > 63) b = 63;
            if (b < 0)  b = 0;
            // Exact searchsorted(edges, vn, 'right'): edges k/64 exact in fp32.
            while (b > 0  && vn <  (float)b       * (1.0f / 64.0f)) b--;
            while (b < 63 && vn >= (float)(b + 1) * (1.0f / 64.0f)) b++;
            hist[b]++;
        }
        float H = 0.0f;
        for (int i = 0; i < NXc; i++) {
            float pb = (float)hist[i] * (1.0f / 64.0f);
            H -= pb * logf(pb + 1e-12f);
        }
        if (vmax < 1e-12f) H = 0.0f;
        out[NXc + 1] = H;
    }
}

extern "C" void kernel_launch(void* const* d_in, const int* in_sizes, int n_in,
                              void* d_out, int out_size) {
    const float* u0    = (const float*)d_in[0];
    const float* w1    = (const float*)d_in[1];
    const float* b1    = (const float*)d_in[2];
    const float* w2    = (const float*)d_in[3];
    const float* b2    = (const float*)d_in[4];
    const float* wc    = (const float*)d_in[5];
    const float* bc    = (const float*)d_in[6];
    const float* gamma = (const float*)d_in[7];
    const int*   Nt    = (const int*)d_in[8];
    float* out = (float*)d_out;

    scct_kernel<<<1, 256>>>(u0, w1, b1, w2, b2, wc, bc, gamma, Nt, out);
}

// round 11
// speedup vs baseline: 1.3854x; 1.3854x over previous
#include <cuda_runtime.h>

// SCCT_NGT: 5000-step explicit PDE loop on NX=64 with tiny MLP closure,
// then phi2 = mean(u^2) and histogram entropy H of |u|/max.
//
// One persistent CTA, 256 threads = 8 warps (2/SMSP). Thread t: point
// p = t>>2, sub = t&3 owns an 8-unit slice of the 32 hidden units; quad
// all-reduce via two __shfl_xor hops; lane sub==0 writes the point.
// Per-SMSP MUFU floor: 16 warp-TANH/step @ rt 8 = 128 cyc/step.
//
// R10 = R7 (measured best, 754us) + 2-step loop unroll + core refactor
// (0.5u - u^3 = u*(C1' - u^2), one fewer FMA-class op). Split-store (R9)
// and f32x2 packing (R8) both measured as regressions and are reverted.

#define NXc 64
#define HIDc 16
#define UPT 8   // hidden units per thread

__device__ __forceinline__ float tanhf_mufu(float x) {
    float y; asm("tanh.approx.f32 %0, %1;" : "=f"(y) : "f"(x)); return y;
}

__global__ __launch_bounds__(256, 1)
void scct_kernel(const float* __restrict__ u0,
                 const float* __restrict__ w1, const float* __restrict__ b1,
                 const float* __restrict__ w2, const float* __restrict__ b2,
                 const float* __restrict__ wc, const float* __restrict__ bc,
                 const float* __restrict__ gammap, const int* __restrict__ Ntp,
                 float* __restrict__ out)
{
    __shared__ float ubuf[2][NXc + 2];   // ghost cells at [0] and [NXc+1], always 0
    __shared__ float s2red[NXc];
    __shared__ float vmred[NXc];
    __shared__ int   hist[NXc];

    const int t   = threadIdx.x;
    const int p   = t >> 2;      // grid point 0..63
    const int sub = t & 3;       // 4 threads per point
    const float bmask = (p == 0 || p == NXc - 1) ? 0.0f : 1.0f;  // Dirichlet

    const float gamma = gammap[0];
    const int   Nt    = Ntp[0];
    const float bcv   = bc[0];

    const float DTf  = (float)1e-4;
    const float R2DX = 31.5f;     // 1/(2*DX), exact
    const float RDX2 = 3969.0f;   // 1/DX^2, exact

    // Masked per-thread update constants (zero on boundary threads -> un = 0).
    const float DTf_m  = DTf * bmask;
    const float DTg_m  = DTf * gamma * bmask;
    const float DTgb_m = DTf * gamma * bcv * bmask;
    const float K08R   = 0.8f * RDX2;        // core: (um+up) coeff
    const float C1     = 0.5f - 2.0f * K08R; // core: uc coeff

    // This thread's 8-unit weight slice, stencil pre-folded:
    //   z_j = um*(RDX2*wq - R2DX*wb) + uc*(wa - 2*RDX2*wq)
    //       + up*(R2DX*wb + RDX2*wq) + bb
    const float* W  = (sub >> 1) ? w2 : w1;
    const float* Bp = (sub >> 1) ? b2 : b1;
    const int j0 = (sub & 1) * UPT;
    float Aw[UPT], Bw[UPT], Cw[UPT], bb[UPT], cwr[UPT];
#pragma unroll
    for (int k = 0; k < UPT; k++) {
        int j = j0 + k;
        float wa = W[j * 3 + 0];
        float wb = W[j * 3 + 1];
        float wq = W[j * 3 + 2];
        Aw[k]  = RDX2 * wq - R2DX * wb;
        Bw[k]  = wa - 2.0f * RDX2 * wq;
        Cw[k]  = R2DX * wb + RDX2 * wq;
        bb[k]  = Bp[j];
        cwr[k] = wc[(sub >> 1) * HIDc + j];
    }

    // Init shared buffers (ghosts zero in both buffers; never rewritten).
    if (t < NXc + 2) { ubuf[0][t] = 0.0f; ubuf[1][t] = 0.0f; }
    __syncthreads();
    if (t < NXc) ubuf[0][t + 1] = u0[t];
    __syncthreads();

#define STEP_BODY(SRC, DST)                                                       \
    {                                                                             \
        const float um = ubuf[SRC][p];                                            \
        const float uc = ubuf[SRC][p + 1];                                        \
        const float up = ubuf[SRC][p + 2];                                        \
        /* core = 0.8*lap + 0.5*uc - uc^3 = (um+up)*K08R + uc*(C1 - uc^2) */      \
        const float q    = fmaf(-uc, uc, C1);                                     \
        const float core = fmaf(um + up, K08R, uc * q);                           \
        const float base = fmaf(DTf_m, core, uc * bmask) + DTgb_m;                \
        float s0 = 0.0f, s1 = 0.0f;                                               \
        _Pragma("unroll")                                                         \
        for (int k = 0; k < UPT; k += 2) {                                        \
            float za = fmaf(up, Cw[k],   fmaf(uc, Bw[k],   fmaf(um, Aw[k],   bb[k])));   \
            float zb = fmaf(up, Cw[k+1], fmaf(uc, Bw[k+1], fmaf(um, Aw[k+1], bb[k+1]))); \
            float ta = tanhf_mufu(za);                                            \
            float tb = tanhf_mufu(zb);                                            \
            s0 = fmaf(cwr[k],   ta, s0);                                          \
            s1 = fmaf(cwr[k+1], tb, s1);                                          \
        }                                                                         \
        float s = s0 + s1;                                                        \
        s += __shfl_xor_sync(0xffffffffu, s, 1);                                  \
        s += __shfl_xor_sync(0xffffffffu, s, 2);                                  \
        if (sub == 0) {                                                           \
            ubuf[DST][p + 1] = fmaf(DTg_m, s, base);                              \
        }                                                                         \
        __syncthreads();                                                          \
    }

    const int nPairs = Nt >> 1;
    for (int it = 0; it < nPairs; ++it) {
        STEP_BODY(0, 1)
        STEP_BODY(1, 0)
    }
    int cur = 0;
    if (Nt & 1) {
        STEP_BODY(0, 1)
        cur = 1;
    }
#undef STEP_BODY

    // ---- Final statistics ----
    const float* uf = &ubuf[cur][1];
    if (t < NXc) {
        float v = uf[t];
        out[t]     = v;
        s2red[t]   = v * v;
        vmred[t]   = fabsf(v);
        hist[t]    = 0;
    }
    __syncthreads();

    if (t == 0) {
        float s2 = 0.0f, vmax = 0.0f;
        for (int i = 0; i < NXc; i++) {
            s2   += s2red[i];
            vmax  = fmaxf(vmax, vmred[i]);
        }
        out[NXc] = s2 * (1.0f / 64.0f);   // phi2 = mean(u^2)

        const float vden = fmaxf(vmax, 1e-12f);
        for (int i = 0; i < NXc; i++) {
            float vn = vmred[i] / vden;   // in [0, 1]
            int b = (int)floorf(vn * 64.0f);
            if (b > 63) b = 63;
            if (b < 0)  b = 0;
            // Exact searchsorted(edges, vn, 'right'): edges k/64 exact in fp32.
            while (b > 0  && vn <  (float)b       * (1.0f / 64.0f)) b--;
            while (b < 63 && vn >= (float)(b + 1) * (1.0f / 64.0f)) b++;
            hist[b]++;
        }
        float H = 0.0f;
        for (int i = 0; i < NXc; i++) {
            float pb = (float)hist[i] * (1.0f / 64.0f);
            H -= pb * logf(pb + 1e-12f);
        }
        if (vmax < 1e-12f) H = 0.0f;
        out[NXc + 1] = H;
    }
}

extern "C" void kernel_launch(void* const* d_in, const int* in_sizes, int n_in,
                              void* d_out, int out_size) {
    const float* u0    = (const float*)d_in[0];
    const float* w1    = (const float*)d_in[1];
    const float* b1    = (const float*)d_in[2];
    const float* w2    = (const float*)d_in[3];
    const float* b2    = (const float*)d_in[4];
    const float* wc    = (const float*)d_in[5];
    const float* bc    = (const float*)d_in[6];
    const float* gamma = (const float*)d_in[7];
    const int*   Nt    = (const int*)d_in[8];
    float* out = (float*)d_out;

    scct_kernel<<<1, 256>>>(u0, w1, b1, w2, b2, wc, bc, gamma, Nt, out);
}